// round 8
// baseline (speedup 1.0000x reference)
#include <cuda_runtime.h>
#include <cuda_fp16.h>
#include <cstdint>

typedef unsigned int u32;

#define B_TOT   4096
#define K_STEPS 512
#define M_ROWS  32
#define THREADS 512

// element pitches
#define WHH_P 136
#define WIH_P 40
#define H16_P 136
#define X16_P 40
#define H32_P 132

// smem byte offsets
#define WHH_OFF  0         // 3*128*136 fp16 = 104448
#define WIH_OFF  104448    // 3*128*40  fp16 = 30720
#define H16_OFF  135168    // 32*136 fp16 = 8704
#define X16_OFF  143872    // 32*40  fp16 = 2560
#define H32_OFF  146432    // 32*132 f32  = 16896
#define HW_OFF   163328    // 8*128 f32 = 4096
#define MISC_OFF 167424    // 984 f32
#define SMEM_TOTAL 171392

__device__ __forceinline__ float tanh_fast(float x) {
    float r; asm("tanh.approx.f32 %0,%1;" : "=f"(r) : "f"(x)); return r;
}
__device__ __forceinline__ float sig_fast(float x) {
    return fmaf(tanh_fast(0.5f * x), 0.5f, 0.5f);
}
__device__ __forceinline__ float sigmoid_exact(float x) {
    x = fminf(fmaxf(x, -30.f), 30.f);
    return __fdividef(1.f, 1.f + __expf(-x));
}
__device__ __forceinline__ void rhs5(const float* y, const float* th, float* d) {
    float f1 = th[0] * y[0] - th[4] * y[1];
    float f2 = th[1] * y[1] - th[5] * y[2];
    float f3 = th[2] * y[2] - th[6] * y[3];
    float f4 = th[3] * y[3] - th[7] * y[4];
    d[0] = -f1; d[1] = f1 - f2; d[2] = f2 - f3; d[3] = f3 - f4; d[4] = f4;
}
__device__ __forceinline__ void mma4(float* c, const u32* a, u32 b0, u32 b1) {
    asm volatile(
        "mma.sync.aligned.m16n8k16.row.col.f32.f16.f16.f32 "
        "{%0,%1,%2,%3},{%4,%5,%6,%7},{%8,%9},{%0,%1,%2,%3};"
        : "+f"(c[0]), "+f"(c[1]), "+f"(c[2]), "+f"(c[3])
        : "r"(a[0]), "r"(a[1]), "r"(a[2]), "r"(a[3]), "r"(b0), "r"(b1));
}
__device__ __forceinline__ void ldsm4(u32* a, u32 sa) {
    asm volatile("ldmatrix.sync.aligned.m8n8.x4.shared.b16 {%0,%1,%2,%3},[%4];"
        : "=r"(a[0]), "=r"(a[1]), "=r"(a[2]), "=r"(a[3]) : "r"(sa));
}

__global__ void __launch_bounds__(THREADS, 1)
rnn_main(const float* __restrict__ y0,
         const float* __restrict__ u_seq,
         const float* __restrict__ dt_seq,
         const float* __restrict__ lift_W,
         const float* __restrict__ lift_b,
         const float* __restrict__ W_ih,
         const float* __restrict__ W_hh,
         const float* __restrict__ b_ih,
         const float* __restrict__ b_hh,
         const float* __restrict__ head_W,
         const float* __restrict__ head_b,
         const float* __restrict__ ujump,
         float* __restrict__ y_out,
         float* __restrict__ theta_out) {
    extern __shared__ char smc[];
    __half* whh16 = (__half*)(smc + WHH_OFF);
    __half* wih16 = (__half*)(smc + WIH_OFF);
    __half* h16   = (__half*)(smc + H16_OFF);
    __half* x16   = (__half*)(smc + X16_OFF);
    float*  h32   = (float*)(smc + H32_OFF);
    float*  hW_s  = (float*)(smc + HW_OFF);
    float*  misc  = (float*)(smc + MISC_OFF);
    float* hb_s = misc;         // 8
    float* lW_s = misc + 8;     // 256
    float* lb_s = misc + 264;   // 32
    float* y_s  = misc + 296;   // 256
    float* th_s = misc + 552;   // 256
    float* u_s  = misc + 808;   // 128
    float* dt_s = misc + 936;   // 32
    float* uj_s = misc + 968;   // 16

    const int t = threadIdx.x, w = t >> 5, lane = t & 31;
    const int qr = lane >> 2, qc = lane & 3;
    const int wg = w >> 3;               // row group 0/1
    const int rb = wg << 4;              // row base 0/16
    const int wj = (w & 7) << 4;         // j-tile base
    const int j_lo = wj + qr, j_hi = j_lo + 8;
    const int R0 = blockIdx.x * M_ROWS;
    const int lr = t & 31;               // row for lift/prefetch

    // ldmatrix lane addressing (A fragments)
    const int lm = lane >> 3;
    const int jr = wj + (lm & 1) * 8 + (lane & 7);
    const int kb = (lm >> 1) * 8;
    u32 smb;
    asm("{ .reg .u64 tt; cvta.to.shared.u64 tt, %1; cvt.u32.u64 %0, tt; }"
        : "=r"(smb) : "l"(smc));
    const u32 whh_lane = smb + WHH_OFF + (u32)(jr * WHH_P + kb) * 2u;
    const u32 wih_lane = smb + WIH_OFF + (u32)(jr * WIH_P + kb) * 2u;

    // ---------------- prologue: stage weights ----------------
    for (int i = t; i < 3 * 128 * 128; i += THREADS) {
        int g = i >> 14, rem = i & 16383, jj = rem >> 7, kk = rem & 127;
        whh16[g * 128 * WHH_P + jj * WHH_P + kk] = __float2half_rn(W_hh[i]);
    }
    for (int i = t; i < 3 * 128 * 32; i += THREADS) {
        int g = i >> 12, rem = i & 4095, jj = rem >> 5, l = rem & 31;
        wih16[g * 128 * WIH_P + jj * WIH_P + l] = __float2half_rn(W_ih[i]);
    }
    for (int i = t; i < 32 * H32_P; i += THREADS) h32[i] = 0.f;
    for (int i = t; i < 1024; i += THREADS) hW_s[i] = head_W[i];
    for (int i = t; i < 256;  i += THREADS) lW_s[i] = lift_W[i];
    if (t < 32) lb_s[t] = lift_b[t];
    if (t < 8)  hb_s[t] = head_b[t];
    if (t < 15) uj_s[t] = ujump[t];
    if (t < 32) {
        #pragma unroll
        for (int i = 0; i < 5; ++i)
            y_s[t * 8 + i] = y0[(R0 + t) * 5 + i] + 0.01f;
    }
    // per-thread biases
    const float bR0  = b_ih[j_lo] + b_hh[j_lo];
    const float bR1  = b_ih[j_hi] + b_hh[j_hi];
    const float bZ0  = b_ih[128 + j_lo] + b_hh[128 + j_lo];
    const float bZ1  = b_ih[128 + j_hi] + b_hh[128 + j_hi];
    const float bNI0 = b_ih[256 + j_lo], bNI1 = b_ih[256 + j_hi];
    const float bNH0 = b_hh[256 + j_lo], bNH1 = b_hh[256 + j_hi];
    __syncthreads();

    float cR[2][4], cZ[2][4], cNI[2][4], cNH[2][4];
    float hp_[2][4] = {{0.f, 0.f, 0.f, 0.f}, {0.f, 0.f, 0.f, 0.f}};

    auto init_accs = [&]() {
        #pragma unroll
        for (int nt = 0; nt < 2; ++nt) {
            cR[nt][0] = bR0;  cR[nt][1] = bR0;  cR[nt][2] = bR1;  cR[nt][3] = bR1;
            cZ[nt][0] = bZ0;  cZ[nt][1] = bZ0;  cZ[nt][2] = bZ1;  cZ[nt][3] = bZ1;
            cNI[nt][0] = bNI0; cNI[nt][1] = bNI0; cNI[nt][2] = bNI1; cNI[nt][3] = bNI1;
            cNH[nt][0] = bNH0; cNH[nt][1] = bNH0; cNH[nt][2] = bNH1; cNH[nt][3] = bNH1;
        }
    };
    auto do_gh = [&]() {
        #pragma unroll
        for (int s = 0; s < 8; ++s) {
            u32 b0[2], b1[2];
            #pragma unroll
            for (int nt = 0; nt < 2; ++nt) {
                const __half* hp = h16 + (qr + 8 * nt + rb) * H16_P + 16 * s + qc * 2;
                b0[nt] = *(const u32*)hp;
                b1[nt] = *(const u32*)(hp + 8);
            }
            u32 a[4];
            ldsm4(a, whh_lane + (u32)s * 32u);
            mma4(cR[0], a, b0[0], b1[0]);  mma4(cR[1], a, b0[1], b1[1]);
            ldsm4(a, whh_lane + 34816u + (u32)s * 32u);
            mma4(cZ[0], a, b0[0], b1[0]);  mma4(cZ[1], a, b0[1], b1[1]);
            ldsm4(a, whh_lane + 69632u + (u32)s * 32u);
            mma4(cNH[0], a, b0[0], b1[0]); mma4(cNH[1], a, b0[1], b1[1]);
        }
    };
    auto do_gi = [&]() {
        #pragma unroll
        for (int s = 0; s < 2; ++s) {
            u32 b0[2], b1[2];
            #pragma unroll
            for (int nt = 0; nt < 2; ++nt) {
                const __half* xp = x16 + (qr + 8 * nt + rb) * X16_P + 16 * s + qc * 2;
                b0[nt] = *(const u32*)xp;
                b1[nt] = *(const u32*)(xp + 8);
            }
            u32 a[4];
            ldsm4(a, wih_lane + (u32)s * 32u);
            mma4(cR[0], a, b0[0], b1[0]);  mma4(cR[1], a, b0[1], b1[1]);
            ldsm4(a, wih_lane + 10240u + (u32)s * 32u);
            mma4(cZ[0], a, b0[0], b1[0]);  mma4(cZ[1], a, b0[1], b1[1]);
            ldsm4(a, wih_lane + 20480u + (u32)s * 32u);
            mma4(cNI[0], a, b0[0], b1[0]); mma4(cNI[1], a, b0[1], b1[1]);
        }
    };

    // ---------------- pre-loop: lift(0) + gi(0) ----------------
    {
        const float* up = u_seq + ((size_t)(R0 + lr) * K_STEPS + 0) * 3;
        float f[8];
        f[0] = up[0]; f[1] = up[1]; f[2] = up[2];
        #pragma unroll
        for (int i = 0; i < 5; ++i) f[3 + i] = y_s[lr * 8 + i];
        int lg = t >> 5;
        if (lg == 0) {
            u_s[lr * 4 + 0] = f[0]; u_s[lr * 4 + 1] = f[1]; u_s[lr * 4 + 2] = f[2];
            dt_s[lr] = dt_seq[(size_t)(R0 + lr) * K_STEPS + 0];
        }
        #pragma unroll
        for (int c = 0; c < 2; ++c) {
            int l = lg * 2 + c;
            float acc = lb_s[l];
            #pragma unroll
            for (int q = 0; q < 8; ++q) acc = fmaf(lW_s[l * 8 + q], f[q], acc);
            x16[lr * X16_P + l] = __float2half_rn(acc * sig_fast(acc));
        }
    }
    __syncthreads();
    init_accs();
    do_gi();

    // ---------------- main loop ----------------
    for (int k = 0; k < K_STEPS; ++k) {
        // (a) epilogue: gates -> h_k
        #pragma unroll
        for (int nt = 0; nt < 2; ++nt) {
            int r0 = qc * 2 + 8 * nt + rb;
            float hn[4];
            #pragma unroll
            for (int c = 0; c < 4; ++c) {
                float gr = sig_fast(cR[nt][c]);
                float gz = sig_fast(cZ[nt][c]);
                float gn = tanh_fast(fmaf(gr, cNH[nt][c], cNI[nt][c]));
                hn[c] = (1.f - gz) * gn + gz * hp_[nt][c];
                hp_[nt][c] = hn[c];
            }
            h32[r0 * H32_P + j_lo]       = hn[0];
            h32[(r0 + 1) * H32_P + j_lo] = hn[1];
            h32[r0 * H32_P + j_hi]       = hn[2];
            h32[(r0 + 1) * H32_P + j_hi] = hn[3];
            h16[r0 * H16_P + j_lo]       = __float2half_rn(hn[0]);
            h16[(r0 + 1) * H16_P + j_lo] = __float2half_rn(hn[1]);
            h16[r0 * H16_P + j_hi]       = __float2half_rn(hn[2]);
            h16[(r0 + 1) * H16_P + j_hi] = __float2half_rn(hn[3]);
        }
        __syncthreads();

        // (b) prefetch u/dt(k+1); gh MMAs for k+1; head(k)
        float uf0 = 0.f, uf1 = 0.f, uf2 = 0.f, dtv = 0.f;
        if (k + 1 < K_STEPS) {
            const float* up = u_seq + ((size_t)(R0 + lr) * K_STEPS + (k + 1)) * 3;
            uf0 = up[0]; uf1 = up[1]; uf2 = up[2];
            dtv = dt_seq[(size_t)(R0 + lr) * K_STEPS + (k + 1)];
            init_accs();
            do_gh();
        }
        if (t < 256) {
            int r = t >> 3, c8 = t & 7;
            float a0 = 0.f, a1 = 0.f, a2 = 0.f, a3 = 0.f;
            const float4* wv = (const float4*)(hW_s + c8 * 128);
            const float4* hv = (const float4*)(h32 + r * H32_P);
            #pragma unroll
            for (int q = 0; q < 8; ++q) {
                float4 aa = wv[4 * q],     bb = hv[4 * q];
                a0 = fmaf(aa.x, bb.x, a0); a0 = fmaf(aa.y, bb.y, a0);
                a0 = fmaf(aa.z, bb.z, a0); a0 = fmaf(aa.w, bb.w, a0);
                aa = wv[4 * q + 1]; bb = hv[4 * q + 1];
                a1 = fmaf(aa.x, bb.x, a1); a1 = fmaf(aa.y, bb.y, a1);
                a1 = fmaf(aa.z, bb.z, a1); a1 = fmaf(aa.w, bb.w, a1);
                aa = wv[4 * q + 2]; bb = hv[4 * q + 2];
                a2 = fmaf(aa.x, bb.x, a2); a2 = fmaf(aa.y, bb.y, a2);
                a2 = fmaf(aa.z, bb.z, a2); a2 = fmaf(aa.w, bb.w, a2);
                aa = wv[4 * q + 3]; bb = hv[4 * q + 3];
                a3 = fmaf(aa.x, bb.x, a3); a3 = fmaf(aa.y, bb.y, a3);
                a3 = fmaf(aa.z, bb.z, a3); a3 = fmaf(aa.w, bb.w, a3);
            }
            float acc = ((a0 + a1) + (a2 + a3)) + hb_s[c8];
            float th = 0.01f + 2.99f * sigmoid_exact(acc);
            th_s[r * 8 + c8] = th;
            theta_out[(((size_t)(R0 + r)) * K_STEPS + k) * 8 + c8] = th;
        }
        __syncthreads();

        // (c) RK4 (warp 0, lane = batch row)
        if (t < 32) {
            int r = t;
            float y[5];
            #pragma unroll
            for (int i = 0; i < 5; ++i) y[i] = y_s[r * 8 + i];
            float u0 = u_s[r * 4], u1 = u_s[r * 4 + 1], u2 = u_s[r * 4 + 2];
            #pragma unroll
            for (int p = 0; p < 5; ++p)
                y[p] += u0 * uj_s[p] + u1 * uj_s[5 + p] + u2 * uj_s[10 + p];
            float th[8];
            #pragma unroll
            for (int i = 0; i < 8; ++i) th[i] = th_s[r * 8 + i];
            float hs = dt_s[r] * 0.1f, hh = 0.5f * hs, h6 = hs * (1.f / 6.f);
            for (int s = 0; s < 10; ++s) {
                float k1[5], k2[5], k3[5], k4[5], yt[5];
                rhs5(y, th, k1);
                #pragma unroll
                for (int i = 0; i < 5; ++i) yt[i] = fmaf(hh, k1[i], y[i]);
                rhs5(yt, th, k2);
                #pragma unroll
                for (int i = 0; i < 5; ++i) yt[i] = fmaf(hh, k2[i], y[i]);
                rhs5(yt, th, k3);
                #pragma unroll
                for (int i = 0; i < 5; ++i) yt[i] = fmaf(hs, k3[i], y[i]);
                rhs5(yt, th, k4);
                #pragma unroll
                for (int i = 0; i < 5; ++i) {
                    float incr = k1[i] + 2.f * k2[i] + 2.f * k3[i] + k4[i];
                    y[i] = fmaxf(fmaf(h6, incr, y[i]), 0.f);
                }
            }
            #pragma unroll
            for (int i = 0; i < 5; ++i) {
                y_s[r * 8 + i] = y[i];
                y_out[(((size_t)(R0 + r)) * K_STEPS + k) * 5 + i] = y[i];
            }
        }
        __syncthreads();

        // (d) lift(k+1) + gi MMAs
        if (k + 1 < K_STEPS) {
            int lg = t >> 5;
            float f[8];
            f[0] = uf0; f[1] = uf1; f[2] = uf2;
            #pragma unroll
            for (int i = 0; i < 5; ++i) f[3 + i] = y_s[lr * 8 + i];
            if (lg == 0) {
                u_s[lr * 4 + 0] = uf0; u_s[lr * 4 + 1] = uf1; u_s[lr * 4 + 2] = uf2;
                dt_s[lr] = dtv;
            }
            #pragma unroll
            for (int c = 0; c < 2; ++c) {
                int l = lg * 2 + c;
                float acc = lb_s[l];
                #pragma unroll
                for (int q = 0; q < 8; ++q) acc = fmaf(lW_s[l * 8 + q], f[q], acc);
                x16[lr * X16_P + l] = __float2half_rn(acc * sig_fast(acc));
            }
            __syncthreads();
            do_gi();
        }
    }
}

extern "C" void kernel_launch(void* const* d_in, const int* in_sizes, int n_in,
                              void* d_out, int out_size) {
    const float* y0     = (const float*)d_in[0];
    const float* u_seq  = (const float*)d_in[1];
    const float* dt_seq = (const float*)d_in[2];
    const float* lift_W = (const float*)d_in[3];
    const float* lift_b = (const float*)d_in[4];
    const float* W_ih   = (const float*)d_in[5];
    const float* W_hh   = (const float*)d_in[6];
    const float* b_ih   = (const float*)d_in[7];
    const float* b_hh   = (const float*)d_in[8];
    const float* head_W = (const float*)d_in[9];
    const float* head_b = (const float*)d_in[10];
    const float* ujump  = (const float*)d_in[11];

    float* y_out     = (float*)d_out;
    float* theta_out = y_out + (size_t)B_TOT * K_STEPS * 5;

    cudaFuncSetAttribute(rnn_main, cudaFuncAttributeMaxDynamicSharedMemorySize,
                         SMEM_TOTAL);
    rnn_main<<<B_TOT / M_ROWS, THREADS, SMEM_TOTAL>>>(
        y0, u_seq, dt_seq, lift_W, lift_b, W_ih, W_hh, b_ih, b_hh,
        head_W, head_b, ujump, y_out, theta_out);
}

// round 9
// speedup vs baseline: 2.4501x; 2.4501x over previous
#include <cuda_runtime.h>
#include <cuda_fp16.h>
#include <cstdint>

typedef unsigned int u32;

#define B_TOT   4096
#define K_STEPS 512
#define M_ROWS  32
#define THREADS 256

#define H16_P 136
#define X16_P 40
#define HW_P  136

__device__ __forceinline__ u32 packh2(float a, float b) {
    __half2 h = __floats2half2_rn(a, b);
    return *(u32*)&h;
}
__device__ __forceinline__ float tanh_fast(float x) {
    float r; asm("tanh.approx.f32 %0,%1;" : "=f"(r) : "f"(x)); return r;
}
__device__ __forceinline__ float sig_fast(float x) {
    return fmaf(tanh_fast(0.5f * x), 0.5f, 0.5f);
}
__device__ __forceinline__ float sigmoid_exact(float x) {
    x = fminf(fmaxf(x, -30.f), 30.f);
    return __fdividef(1.f, 1.f + __expf(-x));
}
__device__ __forceinline__ void rhs5(const float* y, const float* th, float* d) {
    float f1 = th[0] * y[0] - th[4] * y[1];
    float f2 = th[1] * y[1] - th[5] * y[2];
    float f3 = th[2] * y[2] - th[6] * y[3];
    float f4 = th[3] * y[3] - th[7] * y[4];
    d[0] = -f1; d[1] = f1 - f2; d[2] = f2 - f3; d[3] = f3 - f4; d[4] = f4;
}
__device__ __forceinline__ void mma4(float* c, const u32* a, u32 b0, u32 b1) {
    asm volatile(
        "mma.sync.aligned.m16n8k16.row.col.f32.f16.f16.f32 "
        "{%0,%1,%2,%3},{%4,%5,%6,%7},{%8,%9},{%0,%1,%2,%3};"
        : "+f"(c[0]), "+f"(c[1]), "+f"(c[2]), "+f"(c[3])
        : "r"(a[0]), "r"(a[1]), "r"(a[2]), "r"(a[3]), "r"(b0), "r"(b1));
}
__device__ __forceinline__ void ldsm4(u32* a, u32 sa) {
    asm volatile("ldmatrix.sync.aligned.m8n8.x4.shared.b16 {%0,%1,%2,%3},[%4];"
        : "=r"(a[0]), "=r"(a[1]), "=r"(a[2]), "=r"(a[3]) : "r"(sa));
}

__global__ void __launch_bounds__(THREADS, 1)
rnn_main(const float* __restrict__ y0,
         const float* __restrict__ u_seq,
         const float* __restrict__ dt_seq,
         const float* __restrict__ lift_W,
         const float* __restrict__ lift_b,
         const float* __restrict__ W_ih,
         const float* __restrict__ W_hh,
         const float* __restrict__ b_ih,
         const float* __restrict__ b_hh,
         const float* __restrict__ head_W,
         const float* __restrict__ head_b,
         const float* __restrict__ ujump,
         float* __restrict__ y_out,
         float* __restrict__ theta_out) {
    __shared__ __half h16[32 * H16_P];      // h fp16 [r][j]
    __shared__ __half x16[32 * X16_P];      // x fp16 [r][l]
    __shared__ __half hW16[8 * HW_P];       // head_W fp16 [c][k]
    __shared__ float  lW_s[256];
    __shared__ float  lb_s[32];
    __shared__ float  hb_s[8];
    __shared__ float  y_s[256];             // [r*8+i]
    __shared__ float  th_s[256];
    __shared__ float  uj_s[15];

    const int t = threadIdx.x, w = t >> 5, lane = t & 31;
    const int qr = lane >> 2, qc = lane & 3;
    const int wj = w * 16;                  // warp's j base
    const int j_lo = wj + qr, j_hi = j_lo + 8;
    const int R0 = blockIdx.x * M_ROWS;

    // ---------------- prologue ----------------
    // A fragments in registers (permanent)
    u32 agh[3][8][4];
    #pragma unroll
    for (int g = 0; g < 3; ++g)
        #pragma unroll
        for (int s = 0; s < 8; ++s) {
            const float* p = W_hh + (g * 128 + j_lo) * 128 + 16 * s + qc * 2;
            agh[g][s][0] = packh2(p[0], p[1]);
            agh[g][s][1] = packh2(p[1024], p[1025]);
            agh[g][s][2] = packh2(p[8], p[9]);
            agh[g][s][3] = packh2(p[1032], p[1033]);
        }
    u32 agi[3][2][4];
    #pragma unroll
    for (int g = 0; g < 3; ++g)
        #pragma unroll
        for (int s = 0; s < 2; ++s) {
            const float* p = W_ih + (g * 128 + j_lo) * 32 + 16 * s + qc * 2;
            agi[g][s][0] = packh2(p[0], p[1]);
            agi[g][s][1] = packh2(p[256], p[257]);
            agi[g][s][2] = packh2(p[8], p[9]);
            agi[g][s][3] = packh2(p[264], p[265]);
        }
    const float bR0  = b_ih[j_lo] + b_hh[j_lo];
    const float bR1  = b_ih[j_hi] + b_hh[j_hi];
    const float bZ0  = b_ih[128 + j_lo] + b_hh[128 + j_lo];
    const float bZ1  = b_ih[128 + j_hi] + b_hh[128 + j_hi];
    const float bNI0 = b_ih[256 + j_lo], bNI1 = b_ih[256 + j_hi];
    const float bNH0 = b_hh[256 + j_lo], bNH1 = b_hh[256 + j_hi];

    for (int i = t; i < 32 * H16_P / 2; i += THREADS) ((u32*)h16)[i] = 0;
    for (int i = t; i < 1024; i += THREADS) {
        int c = i >> 7, kk = i & 127;
        hW16[c * HW_P + kk] = __float2half_rn(head_W[i]);
    }
    for (int i = t; i < 256; i += THREADS) lW_s[i] = lift_W[i];
    if (t < 32) lb_s[t] = lift_b[t];
    if (t < 8)  hb_s[t] = head_b[t];
    if (t < 15) uj_s[t] = ujump[t];
    if (t < 32) {
        #pragma unroll
        for (int i = 0; i < 5; ++i)
            y_s[t * 8 + i] = y0[(R0 + t) * 5 + i] + 0.01f;
    }
    __syncthreads();

    // shared addresses for ldmatrix (head A frags; only meaningful for w<2)
    u32 h16_base;
    asm("{ .reg .u64 tt; cvta.to.shared.u64 tt, %1; cvt.u32.u64 %0, tt; }"
        : "=r"(h16_base) : "l"((const void*)h16));
    const int lm = lane >> 3;
    const u32 head_a_lane = h16_base +
        (u32)(((w << 4) + (lm & 1) * 8 + (lane & 7)) * H16_P + (lm >> 1) * 8) * 2u;

    float cR[4][4], cZ[4][4], cNI[4][4], cNH[4][4];
    float hp_[4][4] = {{0,0,0,0},{0,0,0,0},{0,0,0,0},{0,0,0,0}};

    auto init_accs = [&]() {
        #pragma unroll
        for (int nt = 0; nt < 4; ++nt) {
            cR[nt][0] = bR0;  cR[nt][1] = bR0;  cR[nt][2] = bR1;  cR[nt][3] = bR1;
            cZ[nt][0] = bZ0;  cZ[nt][1] = bZ0;  cZ[nt][2] = bZ1;  cZ[nt][3] = bZ1;
            cNI[nt][0] = bNI0; cNI[nt][1] = bNI0; cNI[nt][2] = bNI1; cNI[nt][3] = bNI1;
            cNH[nt][0] = bNH0; cNH[nt][1] = bNH0; cNH[nt][2] = bNH1; cNH[nt][3] = bNH1;
        }
    };
    auto do_gh = [&]() {
        #pragma unroll
        for (int s = 0; s < 8; ++s) {
            #pragma unroll
            for (int nt = 0; nt < 4; ++nt) {
                const __half* hp = h16 + (qr + 8 * nt) * H16_P + 16 * s + qc * 2;
                u32 b0 = *(const u32*)hp;
                u32 b1 = *(const u32*)(hp + 8);
                mma4(cR[nt],  agh[0][s], b0, b1);
                mma4(cZ[nt],  agh[1][s], b0, b1);
                mma4(cNH[nt], agh[2][s], b0, b1);
            }
        }
    };
    auto do_gi = [&]() {
        #pragma unroll
        for (int s = 0; s < 2; ++s) {
            #pragma unroll
            for (int nt = 0; nt < 4; ++nt) {
                const __half* xp = x16 + (qr + 8 * nt) * X16_P + 16 * s + qc * 2;
                u32 b0 = *(const u32*)xp;
                u32 b1 = *(const u32*)(xp + 8);
                mma4(cR[nt],  agi[0][s], b0, b1);
                mma4(cZ[nt],  agi[1][s], b0, b1);
                mma4(cNI[nt], agi[2][s], b0, b1);
            }
        }
    };
    auto lift = [&](int kidx) {
        int r = t & 31, lg = t >> 5;
        const float* up = u_seq + ((size_t)(R0 + r) * K_STEPS + kidx) * 3;
        float f[8];
        f[0] = up[0]; f[1] = up[1]; f[2] = up[2];
        #pragma unroll
        for (int i = 0; i < 5; ++i) f[3 + i] = y_s[r * 8 + i];
        #pragma unroll
        for (int c = 0; c < 4; ++c) {
            int l = lg * 4 + c;
            float acc = lb_s[l];
            #pragma unroll
            for (int q = 0; q < 8; ++q) acc = fmaf(lW_s[l * 8 + q], f[q], acc);
            x16[r * X16_P + l] = __float2half_rn(acc * sig_fast(acc));
        }
    };

    // RK4 per-lane state (rows: w0 -> 0-15, w1 -> 16-31)
    float ur0 = 0.f, ur1 = 0.f, ur2 = 0.f, dtr = 0.f;
    const int rkrow = (w << 4) + lane;          // valid when w<2 && lane<16
    if (w < 2 && lane < 16) {
        const float* up = u_seq + ((size_t)(R0 + rkrow) * K_STEPS) * 3;
        ur0 = up[0]; ur1 = up[1]; ur2 = up[2];
        dtr = dt_seq[(size_t)(R0 + rkrow) * K_STEPS];
    }

    // pre-loop: x(0), then step-0 MMAs (h16 = 0)
    lift(0);
    __syncthreads();
    init_accs();
    do_gh();
    do_gi();

    // ---------------- main loop ----------------
    for (int k = 0; k < K_STEPS; ++k) {
        // (a) epilogue: gates -> h(k)
        #pragma unroll
        for (int nt = 0; nt < 4; ++nt) {
            int r0 = qc * 2 + 8 * nt;
            float hn[4];
            #pragma unroll
            for (int c = 0; c < 4; ++c) {
                float gr = sig_fast(cR[nt][c]);
                float gz = sig_fast(cZ[nt][c]);
                float gn = tanh_fast(fmaf(gr, cNH[nt][c], cNI[nt][c]));
                hn[c] = (1.f - gz) * gn + gz * hp_[nt][c];
                hp_[nt][c] = hn[c];
            }
            h16[r0 * H16_P + j_lo]       = __float2half_rn(hn[0]);
            h16[(r0 + 1) * H16_P + j_lo] = __float2half_rn(hn[1]);
            h16[r0 * H16_P + j_hi]       = __float2half_rn(hn[2]);
            h16[(r0 + 1) * H16_P + j_hi] = __float2half_rn(hn[3]);
        }
        __syncthreads();   // A: h(k) visible

        // (b) w0-1: head(k) via MMA -> theta -> RK4; w2-7 fall through to gh
        if (w < 2) {
            float cH[4];
            cH[0] = hb_s[qc * 2]; cH[1] = hb_s[qc * 2 + 1];
            cH[2] = cH[0];        cH[3] = cH[1];
            #pragma unroll
            for (int s = 0; s < 8; ++s) {
                u32 a[4];
                ldsm4(a, head_a_lane + (u32)s * 32u);
                u32 b0 = *(const u32*)&hW16[qr * HW_P + 16 * s + qc * 2];
                u32 b1 = *(const u32*)&hW16[qr * HW_P + 16 * s + 8 + qc * 2];
                mma4(cH, a, b0, b1);
            }
            int row0 = (w << 4) + qr, row1 = row0 + 8;
            float t00 = 0.01f + 2.99f * sigmoid_exact(cH[0]);
            float t01 = 0.01f + 2.99f * sigmoid_exact(cH[1]);
            float t10 = 0.01f + 2.99f * sigmoid_exact(cH[2]);
            float t11 = 0.01f + 2.99f * sigmoid_exact(cH[3]);
            th_s[row0 * 8 + qc * 2]     = t00;
            th_s[row0 * 8 + qc * 2 + 1] = t01;
            th_s[row1 * 8 + qc * 2]     = t10;
            th_s[row1 * 8 + qc * 2 + 1] = t11;
            size_t ob0 = (((size_t)(R0 + row0)) * K_STEPS + k) * 8 + qc * 2;
            size_t ob1 = (((size_t)(R0 + row1)) * K_STEPS + k) * 8 + qc * 2;
            theta_out[ob0] = t00; theta_out[ob0 + 1] = t01;
            theta_out[ob1] = t10; theta_out[ob1 + 1] = t11;
            __syncwarp();

            if (lane < 16) {
                int r = rkrow;
                float y[5];
                #pragma unroll
                for (int i = 0; i < 5; ++i) y[i] = y_s[r * 8 + i];
                #pragma unroll
                for (int p = 0; p < 5; ++p)
                    y[p] += ur0 * uj_s[p] + ur1 * uj_s[5 + p] + ur2 * uj_s[10 + p];
                float th[8];
                #pragma unroll
                for (int i = 0; i < 8; ++i) th[i] = th_s[r * 8 + i];
                float hs = dtr * 0.1f, hh = 0.5f * hs, h6 = hs * (1.f / 6.f);
                for (int s = 0; s < 10; ++s) {
                    float k1[5], k2[5], k3[5], k4[5], yt[5];
                    rhs5(y, th, k1);
                    #pragma unroll
                    for (int i = 0; i < 5; ++i) yt[i] = fmaf(hh, k1[i], y[i]);
                    rhs5(yt, th, k2);
                    #pragma unroll
                    for (int i = 0; i < 5; ++i) yt[i] = fmaf(hh, k2[i], y[i]);
                    rhs5(yt, th, k3);
                    #pragma unroll
                    for (int i = 0; i < 5; ++i) yt[i] = fmaf(hs, k3[i], y[i]);
                    rhs5(yt, th, k4);
                    #pragma unroll
                    for (int i = 0; i < 5; ++i) {
                        float incr = k1[i] + 2.f * k2[i] + 2.f * k3[i] + k4[i];
                        y[i] = fmaxf(fmaf(h6, incr, y[i]), 0.f);
                    }
                }
                #pragma unroll
                for (int i = 0; i < 5; ++i) {
                    y_s[r * 8 + i] = y[i];
                    y_out[(((size_t)(R0 + r)) * K_STEPS + k) * 5 + i] = y[i];
                }
                if (k + 1 < K_STEPS) {
                    const float* up = u_seq + ((size_t)(R0 + r) * K_STEPS + (k + 1)) * 3;
                    ur0 = up[0]; ur1 = up[1]; ur2 = up[2];
                    dtr = dt_seq[(size_t)(R0 + r) * K_STEPS + (k + 1)];
                }
            }
        }
        // all warps: recurrent MMAs for k+1 (w0-1 arrive late — by design)
        if (k + 1 < K_STEPS) {
            init_accs();
            do_gh();
        }
        __syncthreads();   // B: y_s visible, all gh done reading h(k)

        // (c) lift(k+1) + gi
        if (k + 1 < K_STEPS) {
            lift(k + 1);
            __syncthreads();   // C: x(k+1) visible
            do_gi();
        }
    }
}

extern "C" void kernel_launch(void* const* d_in, const int* in_sizes, int n_in,
                              void* d_out, int out_size) {
    const float* y0     = (const float*)d_in[0];
    const float* u_seq  = (const float*)d_in[1];
    const float* dt_seq = (const float*)d_in[2];
    const float* lift_W = (const float*)d_in[3];
    const float* lift_b = (const float*)d_in[4];
    const float* W_ih   = (const float*)d_in[5];
    const float* W_hh   = (const float*)d_in[6];
    const float* b_ih   = (const float*)d_in[7];
    const float* b_hh   = (const float*)d_in[8];
    const float* head_W = (const float*)d_in[9];
    const float* head_b = (const float*)d_in[10];
    const float* ujump  = (const float*)d_in[11];

    float* y_out     = (float*)d_out;
    float* theta_out = y_out + (size_t)B_TOT * K_STEPS * 5;

    rnn_main<<<B_TOT / M_ROWS, THREADS>>>(
        y0, u_seq, dt_seq, lift_W, lift_b, W_ih, W_hh, b_ih, b_hh,
        head_W, head_b, ujump, y_out, theta_out);
}